// round 8
// baseline (speedup 1.0000x reference)
#include <cuda_runtime.h>
#include <cuda_bf16.h>
#include <cstdint>

#define BB 4
#define KK 64
#define LL 128
#define DD 768
#define NBK (BB*KK)          // 256
#define NROWS (NBK*LL)       // 32768 per side
#define TROWS (2*NROWS)      // 65536
#define KV 1536              // packed hi|lo row length (bf16)

// ---------------- scratch ----------------
__device__ float g_ctx_n[(size_t)NROWS * DD];
__device__ float g_ent_n[(size_t)NROWS * DD];
__device__ __nv_bfloat16 g_xb[(size_t)TROWS * KV];   // [row][hi 768 | lo 768]
__device__ __nv_bfloat16 g_w1b[(size_t)DD * KV];     // [n][hi 768 | lo 768]
__device__ float g_f[TROWS];
__device__ int   g_amax[NROWS];

// ---------------- helpers ----------------
__device__ __forceinline__ uint32_t smem_u32(const void* p) {
    uint32_t a;
    asm("{ .reg .u64 t; cvta.to.shared.u64 t, %1; cvt.u32.u64 %0, t; }" : "=r"(a) : "l"(p));
    return a;
}
#define CP_ASYNC16(sa, ga) \
    asm volatile("{ .reg .u64 g; cvta.to.global.u64 g, %1; cp.async.cg.shared.global [%0], [g], 16; }" \
        :: "r"(sa), "l"(ga) : "memory")
#define CP_COMMIT() asm volatile("cp.async.commit_group;" ::: "memory")
#define CP_WAIT1()  asm volatile("cp.async.wait_group 1;" ::: "memory")
#define CP_WAIT0()  asm volatile("cp.async.wait_group 0;" ::: "memory")

#define LDSM4(r0, r1, r2, r3, a) \
    asm volatile("ldmatrix.sync.aligned.m8n8.x4.shared.b16 {%0,%1,%2,%3}, [%4];" \
        : "=r"(r0), "=r"(r1), "=r"(r2), "=r"(r3) : "r"(a))

#define MMA16816(d, a, b) \
    asm volatile("mma.sync.aligned.m16n8k16.row.col.f32.bf16.bf16.f32 " \
        "{%0,%1,%2,%3},{%4,%5,%6,%7},{%8,%9},{%0,%1,%2,%3};" \
        : "+f"((d)[0]), "+f"((d)[1]), "+f"((d)[2]), "+f"((d)[3]) \
        : "r"((a)[0]), "r"((a)[1]), "r"((a)[2]), "r"((a)[3]), "r"((b)[0]), "r"((b)[1]))

// ---------- packed f32x2 (scores kernel) ----------
__device__ __forceinline__ unsigned long long pk2(float lo, float hi) {
    unsigned long long r;
    asm("mov.b64 %0, {%1,%2};" : "=l"(r) : "f"(lo), "f"(hi));
    return r;
}
__device__ __forceinline__ void upk2(unsigned long long v, float& lo, float& hi) {
    asm("mov.b64 {%0,%1}, %2;" : "=f"(lo), "=f"(hi) : "l"(v));
}
__device__ __forceinline__ void ffma2(unsigned long long& d,
                                      unsigned long long a, unsigned long long b) {
    asm("fma.rn.f32x2 %0, %1, %2, %0;" : "+l"(d) : "l"(a), "l"(b));
}

// ---------------------------------------------------------------
// K0: w1 -> transposed bf16 hi/lo
// ---------------------------------------------------------------
__global__ void __launch_bounds__(256) k_prep_w1(const float* __restrict__ w1) {
    int n = blockIdx.x;
    for (int k = threadIdx.x; k < DD; k += 256) {
        float v = w1[(size_t)k * DD + n];
        __nv_bfloat16 h = __float2bfloat16(v);
        g_w1b[(size_t)n * KV + k] = h;
        g_w1b[(size_t)n * KV + DD + k] = __float2bfloat16(v - __bfloat162float(h));
    }
}

// ---------------------------------------------------------------
// K1: normalize rows -> fp32 (scores) + packed bf16 hi|lo (MLP)
// ---------------------------------------------------------------
__global__ void __launch_bounds__(192) k_normalize(const float* __restrict__ ctxt) {
    __shared__ float red[6];
    int r = blockIdx.x;
    int tid = threadIdx.x;
    const float4* src = (const float4*)(ctxt + (size_t)r * DD);
    float4 v = src[tid];
    float ss = v.x*v.x + v.y*v.y + v.z*v.z + v.w*v.w;
    #pragma unroll
    for (int o = 16; o; o >>= 1) ss += __shfl_xor_sync(0xffffffffu, ss, o);
    if ((tid & 31) == 0) red[tid >> 5] = ss;
    __syncthreads();
    float tot = red[0] + red[1] + red[2] + red[3] + red[4] + red[5];
    float inv = 1.0f / sqrtf(tot);
    int l  = r % LL;
    int s  = (r / LL) & 1;
    int bk = r / (2 * LL);
    size_t row32 = (size_t)bk * LL + l;
    float4 o = make_float4(v.x*inv, v.y*inv, v.z*inv, v.w*inv);
    ((float4*)((s == 0 ? g_ctx_n : g_ent_n) + row32 * DD))[tid] = o;
    size_t urow = (size_t)s * NROWS + row32;
    __nv_bfloat16 h0 = __float2bfloat16(o.x), h1 = __float2bfloat16(o.y);
    __nv_bfloat16 h2 = __float2bfloat16(o.z), h3 = __float2bfloat16(o.w);
    __nv_bfloat162* ph = (__nv_bfloat162*)(g_xb + urow * KV) + tid * 2;
    __nv_bfloat162* pl = (__nv_bfloat162*)(g_xb + urow * KV + DD) + tid * 2;
    ph[0] = __nv_bfloat162(h0, h1);
    ph[1] = __nv_bfloat162(h2, h3);
    pl[0] = __nv_bfloat162(__float2bfloat16(o.x - __bfloat162float(h0)),
                           __float2bfloat16(o.y - __bfloat162float(h1)));
    pl[1] = __nv_bfloat162(__float2bfloat16(o.z - __bfloat162float(h2)),
                           __float2bfloat16(o.w - __bfloat162float(h3)));
}

// ---------------------------------------------------------------
// K2: fp32 cosine scores + argmax (exact; argmax is tie-sensitive)
// ---------------------------------------------------------------
__global__ void __launch_bounds__(256) k_scores() {
    __shared__ float As[16 * 128];
    __shared__ float Bs[16 * 128];
    __shared__ float sval[128 * 17];
    __shared__ int   sidx[128 * 17];

    int bk = blockIdx.x;
    const float* ctxp = g_ctx_n + (size_t)bk * LL * DD;
    const float* entp = g_ent_n + (size_t)bk * LL * DD;
    int tid = threadIdx.x;
    int tm = tid & 15, tn = tid >> 4;
    int m0 = tm * 8, n0 = tn * 8;

    unsigned long long c2[8][4];
    #pragma unroll
    for (int i = 0; i < 8; i++)
        #pragma unroll
        for (int j = 0; j < 4; j++) c2[i][j] = 0ULL;

    int mrow = tid & 127;
    int hf = tid >> 7;

    for (int kt = 0; kt < 48; kt++) {
        __syncthreads();
        const float4* a4 = (const float4*)(ctxp + (size_t)mrow * DD + kt * 16);
        const float4* b4 = (const float4*)(entp + (size_t)mrow * DD + kt * 16);
        #pragma unroll
        for (int u = 0; u < 2; u++) {
            int kq = hf * 2 + u;
            float4 v = a4[kq];
            int k4 = kq * 4;
            As[(k4+0)*128+mrow] = v.x; As[(k4+1)*128+mrow] = v.y;
            As[(k4+2)*128+mrow] = v.z; As[(k4+3)*128+mrow] = v.w;
            v = b4[kq];
            Bs[(k4+0)*128+mrow] = v.x; Bs[(k4+1)*128+mrow] = v.y;
            Bs[(k4+2)*128+mrow] = v.z; Bs[(k4+3)*128+mrow] = v.w;
        }
        __syncthreads();
        #pragma unroll
        for (int kk = 0; kk < 16; kk++) {
            float4 aA = *(const float4*)(As + kk*128 + m0);
            float4 aB = *(const float4*)(As + kk*128 + m0 + 4);
            float4 bA = *(const float4*)(Bs + kk*128 + n0);
            float4 bB = *(const float4*)(Bs + kk*128 + n0 + 4);
            unsigned long long ap[8], bp[4];
            ap[0]=pk2(aA.x,aA.x); ap[1]=pk2(aA.y,aA.y); ap[2]=pk2(aA.z,aA.z); ap[3]=pk2(aA.w,aA.w);
            ap[4]=pk2(aB.x,aB.x); ap[5]=pk2(aB.y,aB.y); ap[6]=pk2(aB.z,aB.z); ap[7]=pk2(aB.w,aB.w);
            bp[0]=pk2(bA.x,bA.y); bp[1]=pk2(bA.z,bA.w); bp[2]=pk2(bB.x,bB.y); bp[3]=pk2(bB.z,bB.w);
            #pragma unroll
            for (int i = 0; i < 8; i++)
                #pragma unroll
                for (int j = 0; j < 4; j++) ffma2(c2[i][j], ap[i], bp[j]);
        }
    }

    #pragma unroll
    for (int i = 0; i < 8; i++) {
        float bv = -3.4e38f; int bi = 0;
        #pragma unroll
        for (int j = 0; j < 4; j++) {
            float lo, hi; upk2(c2[i][j], lo, hi);
            int n = n0 + 2 * j;
            if (lo > bv) { bv = lo; bi = n; }
            if (hi > bv) { bv = hi; bi = n + 1; }
        }
        sval[(m0 + i) * 17 + tn] = bv;
        sidx[(m0 + i) * 17 + tn] = bi;
    }
    __syncthreads();
    if (tid < 128) {
        float bv = sval[tid * 17]; int bi = sidx[tid * 17];
        #pragma unroll
        for (int t = 1; t < 16; t++) {
            float v = sval[tid * 17 + t];
            if (v > bv) { bv = v; bi = sidx[tid * 17 + t]; }
        }
        g_amax[bk * LL + tid] = bi;
    }
}

// ---------------------------------------------------------------
// K3 v5: exact R4 pipeline shape (128x128 tile, k=64 stage, 72
// stages, 3-stage 64KB ring, 1 CTA/SM) + product-major MMA order
// (16 independent accumulators between reuses -> no RAW stalls).
// ---------------------------------------------------------------
#define TILE16K 16384
#define STAGE_B (4 * TILE16K)                  // 64 KB
#define NSTAGE 3
#define MLP_SMEM (NSTAGE * STAGE_B + 128 * 17 * 4)   // 196608 + 8704

__global__ void __launch_bounds__(256, 1) k_mlp_mma(const float* __restrict__ b1,
                                                    const float* __restrict__ w2,
                                                    const float* __restrict__ b2) {
    extern __shared__ char sm[];
    uint32_t sb = smem_u32(sm);
    float* red = (float*)(sm + NSTAGE * STAGE_B);

    int tid = threadIdx.x, lane = tid & 31, w = tid >> 5;
    int wm = w & 1, wn = w >> 1;
    size_t rowbase = (size_t)blockIdx.x * 128;

    // ---- producer mapping: thread -> (row lr, 64B half), 4x16B per tile ----
    int lr = tid >> 1;
    uint32_t lq = (uint32_t)(tid & 1) * 64;              // byte base in 128B row
    uint32_t swst = ((uint32_t)(lr & 7)) << 4;           // store-side swizzle
    uint32_t s_row = (uint32_t)lr * 128;
    const char* gA = (const char*)(g_xb + (rowbase + (size_t)lr) * KV);

    #define ISSUE(t) do {                                                        \
        int _nt = (t) / 12, _kt = (t) % 12, _sl = (t) % NSTAGE;                   \
        const char* _ga = gA + _kt * 128;                                         \
        const char* _gb = (const char*)(g_w1b + ((size_t)(_nt * 128) + lr) * KV)  \
                          + _kt * 128;                                            \
        uint32_t _st = sb + _sl * STAGE_B + s_row;                                \
        _Pragma("unroll")                                                         \
        for (int _q = 0; _q < 4; _q++) {                                          \
            uint32_t _cb = lq + _q * 16;                                          \
            uint32_t _so = _st + (_cb ^ swst);                                    \
            CP_ASYNC16(_so,                 _ga + _cb);          /* A hi */       \
            CP_ASYNC16(_so + TILE16K,       _ga + 1536 + _cb);   /* A lo */       \
            CP_ASYNC16(_so + 2 * TILE16K,   _gb + _cb);          /* B hi */       \
            CP_ASYNC16(_so + 3 * TILE16K,   _gb + 1536 + _cb);   /* B lo */       \
        }                                                                         \
        CP_COMMIT();                                                              \
    } while (0)

    // ---- consumer (ldmatrix) mapping ----
    int l15 = lane & 15;
    uint32_t sx = ((uint32_t)(lane & 7)) << 4;           // load-side swizzle
    uint32_t l16 = (uint32_t)(lane >> 4) * 16;
    uint32_t aoff  = (uint32_t)(wm * 64 + l15) * 128;
    uint32_t boff0 = (uint32_t)(wn * 32 + l15) * 128;
    uint32_t boff1 = boff0 + 16 * 128;

    float rs[4][2];
    #pragma unroll
    for (int i = 0; i < 4; i++) { rs[i][0] = 0.f; rs[i][1] = 0.f; }
    float acc[4][4][4];

    ISSUE(0);
    ISSUE(1);

    for (int t = 0; t < 72; t++) {
        int nt = t / 12, kt = t % 12, slot = t % NSTAGE;
        if (t < 71) CP_WAIT1(); else CP_WAIT0();
        __syncthreads();
        if (t + 2 < 72) ISSUE(t + 2);

        if (kt == 0) {
            #pragma unroll
            for (int i = 0; i < 4; i++)
                #pragma unroll
                for (int j = 0; j < 4; j++)
                    #pragma unroll
                    for (int q = 0; q < 4; q++) acc[i][j][q] = 0.f;
        }

        uint32_t stg = sb + slot * STAGE_B;
        #pragma unroll
        for (int kk = 0; kk < 4; kk++) {
            uint32_t kb = ((uint32_t)(kk * 32) + l16) ^ sx;
            uint32_t ah[4][4], al[4][4], th[2][4], tl[2][4];
            #pragma unroll
            for (int i = 0; i < 4; i++) {
                uint32_t ra = stg + aoff + (uint32_t)(i * 16 * 128) + kb;
                LDSM4(ah[i][0], ah[i][1], ah[i][2], ah[i][3], ra);
                LDSM4(al[i][0], al[i][1], al[i][2], al[i][3], ra + TILE16K);
            }
            LDSM4(th[0][0], th[0][1], th[0][2], th[0][3], stg + 2*TILE16K + boff0 + kb);
            LDSM4(th[1][0], th[1][1], th[1][2], th[1][3], stg + 2*TILE16K + boff1 + kb);
            LDSM4(tl[0][0], tl[0][1], tl[0][2], tl[0][3], stg + 3*TILE16K + boff0 + kb);
            LDSM4(tl[1][0], tl[1][1], tl[1][2], tl[1][3], stg + 3*TILE16K + boff1 + kb);
            uint32_t bh[4][2], bl[4][2];
            #pragma unroll
            for (int j = 0; j < 4; j++) {
                bh[j][0] = th[j >> 1][j & 1]; bh[j][1] = th[j >> 1][(j & 1) + 2];
                bl[j][0] = tl[j >> 1][j & 1]; bl[j][1] = tl[j >> 1][(j & 1) + 2];
            }
            // product-major: 16 independent accumulators between reuses
            #pragma unroll
            for (int i = 0; i < 4; i++)
                #pragma unroll
                for (int j = 0; j < 4; j++)
                    MMA16816(acc[i][j], ah[i], bh[j]);   // hi*hi
            #pragma unroll
            for (int i = 0; i < 4; i++)
                #pragma unroll
                for (int j = 0; j < 4; j++)
                    MMA16816(acc[i][j], ah[i], bl[j]);   // hi*lo
            #pragma unroll
            for (int i = 0; i < 4; i++)
                #pragma unroll
                for (int j = 0; j < 4; j++)
                    MMA16816(acc[i][j], al[i], bh[j]);   // lo*hi
        }

        if (kt == 11) {
            #pragma unroll
            for (int j = 0; j < 4; j++) {
                int col = nt * 128 + wn * 32 + j * 8 + (lane & 3) * 2;
                float b1lo = __ldg(b1 + col), b1hi = __ldg(b1 + col + 1);
                float w2lo = __ldg(w2 + col), w2hi = __ldg(w2 + col + 1);
                #pragma unroll
                for (int i = 0; i < 4; i++) {
                    rs[i][0] += fmaxf(acc[i][j][0] + b1lo, 0.f) * w2lo
                              + fmaxf(acc[i][j][1] + b1hi, 0.f) * w2hi;
                    rs[i][1] += fmaxf(acc[i][j][2] + b1lo, 0.f) * w2lo
                              + fmaxf(acc[i][j][3] + b1hi, 0.f) * w2hi;
                }
            }
        }
    }
    #undef ISSUE

    // cross-thread row reduction: 16 contributors per row
    __syncthreads();
    int rcol = wn * 4 + (lane & 3);
    #pragma unroll
    for (int i = 0; i < 4; i++) {
        int row = wm * 64 + i * 16 + (lane >> 2);
        red[row * 17 + rcol] = rs[i][0];
        red[(row + 8) * 17 + rcol] = rs[i][1];
    }
    __syncthreads();
    if (tid < 128) {
        float s = b2[0];
        #pragma unroll
        for (int t = 0; t < 16; t++) s += red[tid * 17 + t];
        g_f[rowbase + tid] = s;
    }
}

// ---------------------------------------------------------------
// K4: out = f(ctx_n) + f(ent_n[argmax])
// ---------------------------------------------------------------
__global__ void k_combine(float* __restrict__ out) {
    int i = blockIdx.x * 256 + threadIdx.x;
    int bk = i / LL;
    out[i] = g_f[i] + g_f[NROWS + bk * LL + g_amax[i]];
}

extern "C" void kernel_launch(void* const* d_in, const int* in_sizes, int n_in,
                              void* d_out, int out_size) {
    const float* context = (const float*)d_in[0];
    const float* w1 = (const float*)d_in[1];
    const float* b1 = (const float*)d_in[2];
    const float* w2 = (const float*)d_in[3];
    const float* b2 = (const float*)d_in[4];
    float* out = (float*)d_out;

    k_prep_w1<<<DD, 256>>>(w1);
    k_normalize<<<NBK * 2 * LL, 192>>>(context);
    k_scores<<<NBK, 256>>>();
    cudaFuncSetAttribute(k_mlp_mma, cudaFuncAttributeMaxDynamicSharedMemorySize, MLP_SMEM);
    k_mlp_mma<<<TROWS / 128, 256, MLP_SMEM>>>(b1, w2, b2);
    k_combine<<<NROWS / 256, 256>>>(out);
}

// round 9
// speedup vs baseline: 1.0897x; 1.0897x over previous
#include <cuda_runtime.h>
#include <cuda_bf16.h>
#include <cstdint>

#define BB 4
#define KK 64
#define LL 128
#define DD 768
#define NBK (BB*KK)          // 256
#define NROWS (NBK*LL)       // 32768 per side
#define TROWS (2*NROWS)      // 65536
#define KV 1536              // packed hi|lo row length (bf16)

// ---------------- scratch ----------------
__device__ float g_ctx_n[(size_t)NROWS * DD];
__device__ float g_ent_n[(size_t)NROWS * DD];
__device__ __nv_bfloat16 g_xb[(size_t)TROWS * KV];   // [row][hi 768 | lo 768]
__device__ __nv_bfloat16 g_w1b[(size_t)DD * KV];     // [n][hi 768 | lo 768]
__device__ float g_f[TROWS];
__device__ int   g_amax[NROWS];

// ---------------- helpers ----------------
__device__ __forceinline__ uint32_t smem_u32(const void* p) {
    uint32_t a;
    asm("{ .reg .u64 t; cvta.to.shared.u64 t, %1; cvt.u32.u64 %0, t; }" : "=r"(a) : "l"(p));
    return a;
}
#define CP_ASYNC16(sa, ga) \
    asm volatile("{ .reg .u64 g; cvta.to.global.u64 g, %1; cp.async.cg.shared.global [%0], [g], 16; }" \
        :: "r"(sa), "l"(ga) : "memory")
#define CP_COMMIT() asm volatile("cp.async.commit_group;" ::: "memory")
#define CP_WAIT0()  asm volatile("cp.async.wait_group 0;" ::: "memory")

#define LDSM4(r, a) \
    asm volatile("ldmatrix.sync.aligned.m8n8.x4.shared.b16 {%0,%1,%2,%3}, [%4];" \
        : "=r"((r)[0]), "=r"((r)[1]), "=r"((r)[2]), "=r"((r)[3]) : "r"(a))

#define MMA16816(d, a, b0, b1) \
    asm volatile("mma.sync.aligned.m16n8k16.row.col.f32.bf16.bf16.f32 " \
        "{%0,%1,%2,%3},{%4,%5,%6,%7},{%8,%9},{%0,%1,%2,%3};" \
        : "+f"((d)[0]), "+f"((d)[1]), "+f"((d)[2]), "+f"((d)[3]) \
        : "r"((a)[0]), "r"((a)[1]), "r"((a)[2]), "r"((a)[3]), "r"(b0), "r"(b1))

// ---------- packed f32x2 (scores kernel) ----------
__device__ __forceinline__ unsigned long long pk2(float lo, float hi) {
    unsigned long long r;
    asm("mov.b64 %0, {%1,%2};" : "=l"(r) : "f"(lo), "f"(hi));
    return r;
}
__device__ __forceinline__ void upk2(unsigned long long v, float& lo, float& hi) {
    asm("mov.b64 {%0,%1}, %2;" : "=f"(lo), "=f"(hi) : "l"(v));
}
__device__ __forceinline__ void ffma2(unsigned long long& d,
                                      unsigned long long a, unsigned long long b) {
    asm("fma.rn.f32x2 %0, %1, %2, %0;" : "+l"(d) : "l"(a), "l"(b));
}

// ---------------------------------------------------------------
// K0: w1 -> transposed bf16 hi/lo
// ---------------------------------------------------------------
__global__ void __launch_bounds__(256) k_prep_w1(const float* __restrict__ w1) {
    int n = blockIdx.x;
    for (int k = threadIdx.x; k < DD; k += 256) {
        float v = w1[(size_t)k * DD + n];
        __nv_bfloat16 h = __float2bfloat16(v);
        g_w1b[(size_t)n * KV + k] = h;
        g_w1b[(size_t)n * KV + DD + k] = __float2bfloat16(v - __bfloat162float(h));
    }
}

// ---------------------------------------------------------------
// K1: normalize rows -> fp32 (scores) + packed bf16 hi|lo (MLP)
// ---------------------------------------------------------------
__global__ void __launch_bounds__(192) k_normalize(const float* __restrict__ ctxt) {
    __shared__ float red[6];
    int r = blockIdx.x;
    int tid = threadIdx.x;
    const float4* src = (const float4*)(ctxt + (size_t)r * DD);
    float4 v = src[tid];
    float ss = v.x*v.x + v.y*v.y + v.z*v.z + v.w*v.w;
    #pragma unroll
    for (int o = 16; o; o >>= 1) ss += __shfl_xor_sync(0xffffffffu, ss, o);
    if ((tid & 31) == 0) red[tid >> 5] = ss;
    __syncthreads();
    float tot = red[0] + red[1] + red[2] + red[3] + red[4] + red[5];
    float inv = 1.0f / sqrtf(tot);
    int l  = r % LL;
    int s  = (r / LL) & 1;
    int bk = r / (2 * LL);
    size_t row32 = (size_t)bk * LL + l;
    float4 o = make_float4(v.x*inv, v.y*inv, v.z*inv, v.w*inv);
    ((float4*)((s == 0 ? g_ctx_n : g_ent_n) + row32 * DD))[tid] = o;
    size_t urow = (size_t)s * NROWS + row32;
    __nv_bfloat16 h0 = __float2bfloat16(o.x), h1 = __float2bfloat16(o.y);
    __nv_bfloat16 h2 = __float2bfloat16(o.z), h3 = __float2bfloat16(o.w);
    __nv_bfloat162* ph = (__nv_bfloat162*)(g_xb + urow * KV) + tid * 2;
    __nv_bfloat162* pl = (__nv_bfloat162*)(g_xb + urow * KV + DD) + tid * 2;
    ph[0] = __nv_bfloat162(h0, h1);
    ph[1] = __nv_bfloat162(h2, h3);
    pl[0] = __nv_bfloat162(__float2bfloat16(o.x - __bfloat162float(h0)),
                           __float2bfloat16(o.y - __bfloat162float(h1)));
    pl[1] = __nv_bfloat162(__float2bfloat16(o.z - __bfloat162float(h2)),
                           __float2bfloat16(o.w - __bfloat162float(h3)));
}

// ---------------------------------------------------------------
// K2: fp32 cosine scores + argmax (exact; argmax is tie-sensitive)
// ---------------------------------------------------------------
__global__ void __launch_bounds__(256) k_scores() {
    __shared__ float As[16 * 128];
    __shared__ float Bs[16 * 128];
    __shared__ float sval[128 * 17];
    __shared__ int   sidx[128 * 17];

    int bk = blockIdx.x;
    const float* ctxp = g_ctx_n + (size_t)bk * LL * DD;
    const float* entp = g_ent_n + (size_t)bk * LL * DD;
    int tid = threadIdx.x;
    int tm = tid & 15, tn = tid >> 4;
    int m0 = tm * 8, n0 = tn * 8;

    unsigned long long c2[8][4];
    #pragma unroll
    for (int i = 0; i < 8; i++)
        #pragma unroll
        for (int j = 0; j < 4; j++) c2[i][j] = 0ULL;

    int mrow = tid & 127;
    int hf = tid >> 7;

    for (int kt = 0; kt < 48; kt++) {
        __syncthreads();
        const float4* a4 = (const float4*)(ctxp + (size_t)mrow * DD + kt * 16);
        const float4* b4 = (const float4*)(entp + (size_t)mrow * DD + kt * 16);
        #pragma unroll
        for (int u = 0; u < 2; u++) {
            int kq = hf * 2 + u;
            float4 v = a4[kq];
            int k4 = kq * 4;
            As[(k4+0)*128+mrow] = v.x; As[(k4+1)*128+mrow] = v.y;
            As[(k4+2)*128+mrow] = v.z; As[(k4+3)*128+mrow] = v.w;
            v = b4[kq];
            Bs[(k4+0)*128+mrow] = v.x; Bs[(k4+1)*128+mrow] = v.y;
            Bs[(k4+2)*128+mrow] = v.z; Bs[(k4+3)*128+mrow] = v.w;
        }
        __syncthreads();
        #pragma unroll
        for (int kk = 0; kk < 16; kk++) {
            float4 aA = *(const float4*)(As + kk*128 + m0);
            float4 aB = *(const float4*)(As + kk*128 + m0 + 4);
            float4 bA = *(const float4*)(Bs + kk*128 + n0);
            float4 bB = *(const float4*)(Bs + kk*128 + n0 + 4);
            unsigned long long ap[8], bp[4];
            ap[0]=pk2(aA.x,aA.x); ap[1]=pk2(aA.y,aA.y); ap[2]=pk2(aA.z,aA.z); ap[3]=pk2(aA.w,aA.w);
            ap[4]=pk2(aB.x,aB.x); ap[5]=pk2(aB.y,aB.y); ap[6]=pk2(aB.z,aB.z); ap[7]=pk2(aB.w,aB.w);
            bp[0]=pk2(bA.x,bA.y); bp[1]=pk2(bA.z,bA.w); bp[2]=pk2(bB.x,bB.y); bp[3]=pk2(bB.z,bB.w);
            #pragma unroll
            for (int i = 0; i < 8; i++)
                #pragma unroll
                for (int j = 0; j < 4; j++) ffma2(c2[i][j], ap[i], bp[j]);
        }
    }

    #pragma unroll
    for (int i = 0; i < 8; i++) {
        float bv = -3.4e38f; int bi = 0;
        #pragma unroll
        for (int j = 0; j < 4; j++) {
            float lo, hi; upk2(c2[i][j], lo, hi);
            int n = n0 + 2 * j;
            if (lo > bv) { bv = lo; bi = n; }
            if (hi > bv) { bv = hi; bi = n + 1; }
        }
        sval[(m0 + i) * 17 + tn] = bv;
        sidx[(m0 + i) * 17 + tn] = bi;
    }
    __syncthreads();
    if (tid < 128) {
        float bv = sval[tid * 17]; int bi = sidx[tid * 17];
        #pragma unroll
        for (int t = 1; t < 16; t++) {
            float v = sval[tid * 17 + t];
            if (v > bv) { bv = v; bi = sidx[tid * 17 + t]; }
        }
        g_amax[bk * LL + tid] = bi;
    }
}

// ---------------------------------------------------------------
// K3 v6: MLP bf16 hi/lo 3-product mma.sync, WIDE CTA.
// 512 threads (16 warps, 4 warps/SMSP), tile 256 rows x 128 cols,
// k=64 stages (72 total), 2-stage 96KB cp.async ring, grid 256.
// Warp tile 64x32 (4M x 4N), same 4:1 MMA:LDSM ratio as R4 but
// double the warps per SMSP to hide barrier/LDSM/MMA latency.
// ---------------------------------------------------------------
#define A_HI 0
#define A_LO 32768
#define B_HI 65536
#define B_LO 81920
#define STAGE_B 98304                       // 96 KB
#define MLP_SMEM (2 * STAGE_B + 256 * 17 * 4)   // 196608 + 17408 = 214016

__global__ void __launch_bounds__(512, 1) k_mlp_mma(const float* __restrict__ b1,
                                                    const float* __restrict__ w2,
                                                    const float* __restrict__ b2) {
    extern __shared__ char sm[];
    uint32_t sb = smem_u32(sm);
    float* red = (float*)(sm + 2 * STAGE_B);

    int tid = threadIdx.x, lane = tid & 31, w = tid >> 5;
    int wm = w & 3, wn = w >> 2;
    size_t rowbase = (size_t)blockIdx.x * 256;

    // ---- producer mapping ----
    // A: 2 threads per row. lr = row (0..255), half = 64B chunk of the 128B line
    int lr = tid >> 1;
    uint32_t a_cb = (uint32_t)(tid & 1) * 64;
    uint32_t a_swz = ((uint32_t)(lr & 7)) << 4;
    uint32_t a_srow = (uint32_t)lr * 128;
    const char* gA = (const char*)(g_xb + (rowbase + (size_t)lr) * KV);
    // B: 4 threads per n-row. nr = 0..127, q: 0/1 = hi halves, 2/3 = lo halves
    int nr = tid >> 2;
    int q  = tid & 3;
    uint32_t b_cb = (uint32_t)(q & 1) * 64;
    uint32_t b_swz = ((uint32_t)(nr & 7)) << 4;
    uint32_t b_srow = (uint32_t)nr * 128;
    uint32_t b_tile = (q >> 1) ? B_LO : B_HI;
    size_t   b_glo  = (size_t)(q >> 1) * 1536;

    #define ISSUE(t) do {                                                        \
        int _nt = (t) / 12, _kt = (t) % 12;                                       \
        uint32_t _st = sb + (uint32_t)((t) & 1) * STAGE_B;                        \
        const char* _ga = gA + _kt * 128 + a_cb;                                  \
        uint32_t _sa = _st + a_srow;                                              \
        _Pragma("unroll")                                                         \
        for (int _q4 = 0; _q4 < 4; _q4++) {                                       \
            uint32_t _c = (a_cb + _q4 * 16) ^ a_swz;                              \
            CP_ASYNC16(_st + A_HI + a_srow + _c, _ga + _q4 * 16);                 \
            CP_ASYNC16(_st + A_LO + a_srow + _c, _ga + 1536 + _q4 * 16);          \
        }                                                                         \
        const char* _gb = (const char*)(g_w1b + ((size_t)(_nt * 128 + nr)) * KV)  \
                          + b_glo + _kt * 128 + b_cb;                             \
        uint32_t _sb2 = _st + b_tile + b_srow;                                    \
        _Pragma("unroll")                                                         \
        for (int _q4 = 0; _q4 < 4; _q4++)                                         \
            CP_ASYNC16(_sb2 + ((b_cb + _q4 * 16) ^ b_swz), _gb + _q4 * 16);       \
        CP_COMMIT();                                                              \
    } while (0)

    // ---- consumer (ldmatrix) mapping ----
    int l15 = lane & 15;
    uint32_t sx = ((uint32_t)(lane & 7)) << 4;
    uint32_t l16 = (uint32_t)(lane >> 4) * 16;
    uint32_t aoff  = (uint32_t)(wm * 64 + l15) * 128;
    uint32_t boff0 = (uint32_t)(wn * 32 + l15) * 128;
    uint32_t boff1 = boff0 + 2048;

    float rs[4][2];
    #pragma unroll
    for (int i = 0; i < 4; i++) { rs[i][0] = 0.f; rs[i][1] = 0.f; }
    float acc[4][4][4];

    ISSUE(0);

    for (int t = 0; t < 72; t++) {
        int nt = t / 12, kt = t % 12;
        CP_WAIT0();
        __syncthreads();
        if (t + 1 < 72) ISSUE(t + 1);

        if (kt == 0) {
            #pragma unroll
            for (int i = 0; i < 4; i++)
                #pragma unroll
                for (int j = 0; j < 4; j++)
                    #pragma unroll
                    for (int qq = 0; qq < 4; qq++) acc[i][j][qq] = 0.f;
        }

        uint32_t stg = sb + (uint32_t)(t & 1) * STAGE_B;
        #pragma unroll
        for (int kk = 0; kk < 4; kk++) {
            uint32_t kbh = ((uint32_t)(kk * 32) + l16) ^ sx;
            uint32_t kbl = kbh ^ 64;
            uint32_t af[4][4], th0[4], th1[4], tl0[4], tl1[4];

            // A hi + B hi
            #pragma unroll
            for (int i = 0; i < 4; i++)
                LDSM4(af[i], stg + A_HI + aoff + (uint32_t)(i * 2048) + kbh);
            LDSM4(th0, stg + B_HI + boff0 + kbh);
            LDSM4(th1, stg + B_HI + boff1 + kbh);

            // P1: hi * hi
            #pragma unroll
            for (int i = 0; i < 4; i++) {
                MMA16816(acc[i][0], af[i], th0[0], th0[2]);
                MMA16816(acc[i][1], af[i], th0[1], th0[3]);
                MMA16816(acc[i][2], af[i], th1[0], th1[2]);
                MMA16816(acc[i][3], af[i], th1[1], th1[3]);
            }

            // B lo
            LDSM4(tl0, stg + B_LO + boff0 + kbh);
            LDSM4(tl1, stg + B_LO + boff1 + kbh);

            // P2: hi * lo
            #pragma unroll
            for (int i = 0; i < 4; i++) {
                MMA16816(acc[i][0], af[i], tl0[0], tl0[2]);
                MMA16816(acc[i][1], af[i], tl0[1], tl0[3]);
                MMA16816(acc[i][2], af[i], tl1[0], tl1[2]);
                MMA16816(acc[i][3], af[i], tl1[1], tl1[3]);
            }

            // A lo (overwrite af)
            #pragma unroll
            for (int i = 0; i < 4; i++)
                LDSM4(af[i], stg + A_LO + aoff + (uint32_t)(i * 2048) + kbh);

            // P3: lo * hi
            #pragma unroll
            for (int i = 0; i < 4; i++) {
                MMA16816(acc[i][0], af[i], th0[0], th0[2]);
                MMA16816(acc[i][1], af[i], th0[1], th0[3]);
                MMA16816(acc[i][2], af[i], th1[0], th1[2]);
                MMA16816(acc[i][3], af[i], th1[1], th1[3]);
            }
            (void)kbl;
        }

        if (kt == 11) {
            #pragma unroll
            for (int j = 0; j < 4; j++) {
                int col = nt * 128 + wn * 32 + j * 8 + (lane & 3) * 2;
                float b1lo = __ldg(b1 + col), b1hi = __ldg(b1 + col + 1);
                float w2lo = __ldg(w2 + col), w2hi = __ldg(w2 + col + 1);
                #pragma unroll
                for (int i = 0; i < 4; i++) {
                    rs[i][0] += fmaxf(acc[i][j][0] + b1lo, 0.f) * w2lo
                              + fmaxf(acc[i][j][1] + b1hi, 0.f) * w2hi;
                    rs[i][1] += fmaxf(acc[i][j][2] + b1lo, 0.f) * w2lo
                              + fmaxf(acc[i][j][3] + b1hi, 0.f) * w2hi;
                }
            }
        }
    }
    #undef ISSUE

    // cross-thread row reduction: 16 contributors per row
    __syncthreads();
    int rcol = wn * 4 + (lane & 3);
    #pragma unroll
    for (int i = 0; i < 4; i++) {
        int row = wm * 64 + i * 16 + (lane >> 2);
        red[row * 17 + rcol] = rs[i][0];
        red[(row + 8) * 17 + rcol] = rs[i][1];
    }
    __syncthreads();
    if (tid < 256) {
        float s = b2[0];
        #pragma unroll
        for (int t = 0; t < 16; t++) s += red[tid * 17 + t];
        g_f[rowbase + tid] = s;
    }
}

// ---------------------------------------------------------------
// K4: out = f(ctx_n) + f(ent_n[argmax])
// ---------------------------------------------------------------
__global__ void k_combine(float* __restrict__ out) {
    int i = blockIdx.x * 256 + threadIdx.x;
    int bk = i / LL;
    out[i] = g_f[i] + g_f[NROWS + bk * LL + g_amax[i]];
}

extern "C" void kernel_launch(void* const* d_in, const int* in_sizes, int n_in,
                              void* d_out, int out_size) {
    const float* context = (const float*)d_in[0];
    const float* w1 = (const float*)d_in[1];
    const float* b1 = (const float*)d_in[2];
    const float* w2 = (const float*)d_in[3];
    const float* b2 = (const float*)d_in[4];
    float* out = (float*)d_out;

    k_prep_w1<<<DD, 256>>>(w1);
    k_normalize<<<NBK * 2 * LL, 192>>>(context);
    k_scores<<<NBK, 256>>>();
    cudaFuncSetAttribute(k_mlp_mma, cudaFuncAttributeMaxDynamicSharedMemorySize, MLP_SMEM);
    k_mlp_mma<<<TROWS / 256, 512, MLP_SMEM>>>(b1, w2, b2);
    k_combine<<<NROWS / 256, 256>>>(out);
}

// round 14
// speedup vs baseline: 1.4280x; 1.3105x over previous
#include <cuda_runtime.h>
#include <cuda_bf16.h>
#include <cuda_fp16.h>
#include <cstdint>

#define BB 4
#define KK 64
#define LL 128
#define DD 768
#define NBK (BB*KK)          // 256
#define NROWS (NBK*LL)       // 32768 per side
#define TROWS (2*NROWS)      // 65536

// ---------------- scratch ----------------
__device__ float g_ctx_n[(size_t)NROWS * DD];
__device__ float g_ent_n[(size_t)NROWS * DD];
__device__ __half g_xh[(size_t)TROWS * DD];          // normalized rows, fp16
__device__ __half g_w1h[(size_t)DD * 2 * DD];        // [n][hi 768 | lo 768], w1^T * 64
__device__ float g_f[TROWS];
__device__ int   g_amax[NROWS];

// ---------------- helpers ----------------
__device__ __forceinline__ uint32_t smem_u32(const void* p) {
    uint32_t a;
    asm("{ .reg .u64 t; cvta.to.shared.u64 t, %1; cvt.u32.u64 %0, t; }" : "=r"(a) : "l"(p));
    return a;
}
#define CP_ASYNC16(sa, ga) \
    asm volatile("{ .reg .u64 g; cvta.to.global.u64 g, %1; cp.async.cg.shared.global [%0], [g], 16; }" \
        :: "r"(sa), "l"(ga) : "memory")
#define CP_COMMIT() asm volatile("cp.async.commit_group;" ::: "memory")
#define CP_WAIT1()  asm volatile("cp.async.wait_group 1;" ::: "memory")
#define CP_WAIT0()  asm volatile("cp.async.wait_group 0;" ::: "memory")

#define LDSM4(r, a) \
    asm volatile("ldmatrix.sync.aligned.m8n8.x4.shared.b16 {%0,%1,%2,%3}, [%4];" \
        : "=r"((r)[0]), "=r"((r)[1]), "=r"((r)[2]), "=r"((r)[3]) : "r"(a))

#define MMAH(d, a, b0, b1) \
    asm volatile("mma.sync.aligned.m16n8k16.row.col.f32.f16.f16.f32 " \
        "{%0,%1,%2,%3},{%4,%5,%6,%7},{%8,%9},{%0,%1,%2,%3};" \
        : "+f"((d)[0]), "+f"((d)[1]), "+f"((d)[2]), "+f"((d)[3]) \
        : "r"((a)[0]), "r"((a)[1]), "r"((a)[2]), "r"((a)[3]), "r"(b0), "r"(b1))

// ---------- packed f32x2 (scores kernel) ----------
__device__ __forceinline__ unsigned long long pk2(float lo, float hi) {
    unsigned long long r;
    asm("mov.b64 %0, {%1,%2};" : "=l"(r) : "f"(lo), "f"(hi));
    return r;
}
__device__ __forceinline__ void upk2(unsigned long long v, float& lo, float& hi) {
    asm("mov.b64 {%0,%1}, %2;" : "=f"(lo), "=f"(hi) : "l"(v));
}
__device__ __forceinline__ void ffma2(unsigned long long& d,
                                      unsigned long long a, unsigned long long b) {
    asm("fma.rn.f32x2 %0, %1, %2, %0;" : "+l"(d) : "l"(a), "l"(b));
}

// ---------------------------------------------------------------
// K0: w1 -> transposed fp16 hi/lo, scaled by 64 (keeps lo normal-range)
// ---------------------------------------------------------------
__global__ void __launch_bounds__(256) k_prep_w1(const float* __restrict__ w1) {
    int n = blockIdx.x;
    for (int k = threadIdx.x; k < DD; k += 256) {
        float v = w1[(size_t)k * DD + n] * 64.0f;
        __half h = __float2half_rn(v);
        g_w1h[(size_t)n * 1536 + k] = h;
        g_w1h[(size_t)n * 1536 + DD + k] = __float2half_rn(v - __half2float(h));
    }
}

// ---------------------------------------------------------------
// K1: normalize rows -> fp32 (scores) + fp16 (MLP)
// ---------------------------------------------------------------
__global__ void __launch_bounds__(192) k_normalize(const float* __restrict__ ctxt) {
    __shared__ float red[6];
    int r = blockIdx.x;
    int tid = threadIdx.x;
    const float4* src = (const float4*)(ctxt + (size_t)r * DD);
    float4 v = src[tid];
    float ss = v.x*v.x + v.y*v.y + v.z*v.z + v.w*v.w;
    #pragma unroll
    for (int o = 16; o; o >>= 1) ss += __shfl_xor_sync(0xffffffffu, ss, o);
    if ((tid & 31) == 0) red[tid >> 5] = ss;
    __syncthreads();
    float tot = red[0] + red[1] + red[2] + red[3] + red[4] + red[5];
    float inv = 1.0f / sqrtf(tot);
    int l  = r % LL;
    int s  = (r / LL) & 1;
    int bk = r / (2 * LL);
    size_t row32 = (size_t)bk * LL + l;
    float4 o = make_float4(v.x*inv, v.y*inv, v.z*inv, v.w*inv);
    ((float4*)((s == 0 ? g_ctx_n : g_ent_n) + row32 * DD))[tid] = o;
    size_t urow = (size_t)s * NROWS + row32;
    __half2* ph = (__half2*)(g_xh + urow * DD) + tid * 2;
    ph[0] = __floats2half2_rn(o.x, o.y);
    ph[1] = __floats2half2_rn(o.z, o.w);
}

// ---------------------------------------------------------------
// K2: fp32 cosine scores + argmax (exact; argmax is tie-sensitive)
// ---------------------------------------------------------------
__global__ void __launch_bounds__(256) k_scores() {
    __shared__ float As[16 * 128];
    __shared__ float Bs[16 * 128];
    __shared__ float sval[128 * 17];
    __shared__ int   sidx[128 * 17];

    int bk = blockIdx.x;
    const float* ctxp = g_ctx_n + (size_t)bk * LL * DD;
    const float* entp = g_ent_n + (size_t)bk * LL * DD;
    int tid = threadIdx.x;
    int tm = tid & 15, tn = tid >> 4;
    int m0 = tm * 8, n0 = tn * 8;

    unsigned long long c2[8][4];
    #pragma unroll
    for (int i = 0; i < 8; i++)
        #pragma unroll
        for (int j = 0; j < 4; j++) c2[i][j] = 0ULL;

    int mrow = tid & 127;
    int hf = tid >> 7;

    for (int kt = 0; kt < 48; kt++) {
        __syncthreads();
        const float4* a4 = (const float4*)(ctxp + (size_t)mrow * DD + kt * 16);
        const float4* b4 = (const float4*)(entp + (size_t)mrow * DD + kt * 16);
        #pragma unroll
        for (int u = 0; u < 2; u++) {
            int kq = hf * 2 + u;
            float4 v = a4[kq];
            int k4 = kq * 4;
            As[(k4+0)*128+mrow] = v.x; As[(k4+1)*128+mrow] = v.y;
            As[(k4+2)*128+mrow] = v.z; As[(k4+3)*128+mrow] = v.w;
            v = b4[kq];
            Bs[(k4+0)*128+mrow] = v.x; Bs[(k4+1)*128+mrow] = v.y;
            Bs[(k4+2)*128+mrow] = v.z; Bs[(k4+3)*128+mrow] = v.w;
        }
        __syncthreads();
        #pragma unroll
        for (int kk = 0; kk < 16; kk++) {
            float4 aA = *(const float4*)(As + kk*128 + m0);
            float4 aB = *(const float4*)(As + kk*128 + m0 + 4);
            float4 bA = *(const float4*)(Bs + kk*128 + n0);
            float4 bB = *(const float4*)(Bs + kk*128 + n0 + 4);
            unsigned long long ap[8], bp[4];
            ap[0]=pk2(aA.x,aA.x); ap[1]=pk2(aA.y,aA.y); ap[2]=pk2(aA.z,aA.z); ap[3]=pk2(aA.w,aA.w);
            ap[4]=pk2(aB.x,aB.x); ap[5]=pk2(aB.y,aB.y); ap[6]=pk2(aB.z,aB.z); ap[7]=pk2(aB.w,aB.w);
            bp[0]=pk2(bA.x,bA.y); bp[1]=pk2(bA.z,bA.w); bp[2]=pk2(bB.x,bB.y); bp[3]=pk2(bB.z,bB.w);
            #pragma unroll
            for (int i = 0; i < 8; i++)
                #pragma unroll
                for (int j = 0; j < 4; j++) ffma2(c2[i][j], ap[i], bp[j]);
        }
    }

    #pragma unroll
    for (int i = 0; i < 8; i++) {
        float bv = -3.4e38f; int bi = 0;
        #pragma unroll
        for (int j = 0; j < 4; j++) {
            float lo, hi; upk2(c2[i][j], lo, hi);
            int n = n0 + 2 * j;
            if (lo > bv) { bv = lo; bi = n; }
            if (hi > bv) { bv = hi; bi = n + 1; }
        }
        sval[(m0 + i) * 17 + tn] = bv;
        sidx[(m0 + i) * 17 + tn] = bi;
    }
    __syncthreads();
    if (tid < 128) {
        float bv = sval[tid * 17]; int bi = sidx[tid * 17];
        #pragma unroll
        for (int t = 1; t < 16; t++) {
            float v = sval[tid * 17 + t];
            if (v > bv) { bv = v; bi = sidx[tid * 17 + t]; }
        }
        g_amax[bk * LL + tid] = bi;
    }
}

// ---------------------------------------------------------------
// K3 v7b: MLP fp16, 2-product (A fp16 plain, W fp16 hi/lo, W scaled
// x64). 512 threads, tile 256 rows x 128 cols, k=64 stages (72),
// 3-stage 64KB ring w/ wait_group 1, grid 256. Warp tile 64x32.
// FIX vs v7: B lo global offset is 768 ELEMENTS (was 1536 -- byte
// constant wrongly used as element offset).
// ---------------------------------------------------------------
#define A_OFF 0
#define BH_OFF 32768
#define BL_OFF 49152
#define STAGE_B 65536                        // 64 KB
#define MLP_SMEM (3 * STAGE_B + 256 * 17 * 4)    // 196608 + 17408 = 214016
#define INV64 0.015625f

__global__ void __launch_bounds__(512, 1) k_mlp_mma(const float* __restrict__ b1,
                                                    const float* __restrict__ w2,
                                                    const float* __restrict__ b2) {
    extern __shared__ char sm[];
    uint32_t sb = smem_u32(sm);
    float* red = (float*)(sm + 3 * STAGE_B);

    int tid = threadIdx.x, lane = tid & 31, w = tid >> 5;
    int wm = w & 3, wn = w >> 2;
    size_t rowbase = (size_t)blockIdx.x * 256;

    // ---- producer mapping ----
    // A: 256 rows x 128B (64 fp16 per k-chunk); 2 threads/row, 64B each
    int lr = tid >> 1;
    uint32_t a_cb = (uint32_t)(tid & 1) * 64;
    uint32_t a_swz = ((uint32_t)(lr & 7)) << 4;
    uint32_t a_srow = (uint32_t)lr * 128;
    const char* gA = (const char*)(g_xh + (rowbase + (size_t)lr) * DD) + a_cb;
    // B: 128 n-rows x (hi 128B + lo 128B); 4 threads/row: q&1 = 64B half, q>>1 = hi/lo
    int nr = tid >> 2;
    int q  = tid & 3;
    uint32_t b_cb = (uint32_t)(q & 1) * 64;
    uint32_t b_swz = ((uint32_t)(nr & 7)) << 4;
    uint32_t b_srow = (uint32_t)nr * 128;
    uint32_t b_tile = (q >> 1) ? BL_OFF : BH_OFF;
    size_t   b_goff = (size_t)(q >> 1) * DD + (q & 1) * 32;   // ELEMENT offsets

    #define ISSUE(t) do {                                                        \
        int _nt = (t) / 12, _kt = (t) % 12;                                       \
        uint32_t _st = sb + (uint32_t)((t) % 3) * STAGE_B;                        \
        const char* _ga = gA + _kt * 128;                                         \
        _Pragma("unroll")                                                         \
        for (int _q4 = 0; _q4 < 4; _q4++)                                         \
            CP_ASYNC16(_st + A_OFF + a_srow + ((a_cb + _q4 * 16) ^ a_swz),        \
                       _ga + _q4 * 16);                                           \
        const char* _gb = (const char*)(g_w1h                                     \
            + ((size_t)(_nt * 128 + nr)) * 1536 + b_goff + _kt * 64);             \
        uint32_t _sb2 = _st + b_tile + b_srow;                                    \
        _Pragma("unroll")                                                         \
        for (int _q4 = 0; _q4 < 4; _q4++)                                         \
            CP_ASYNC16(_sb2 + ((b_cb + _q4 * 16) ^ b_swz), _gb + _q4 * 16);       \
        CP_COMMIT();                                                              \
    } while (0)

    // ---- consumer (ldmatrix) mapping ----
    int l15 = lane & 15;
    uint32_t sx = ((uint32_t)(lane & 7)) << 4;
    uint32_t l16 = (uint32_t)(lane >> 4) * 16;
    uint32_t aoff  = (uint32_t)(wm * 64 + l15) * 128;
    uint32_t boff0 = (uint32_t)(wn * 32 + l15) * 128;
    uint32_t boff1 = boff0 + 2048;

    float rs[4][2];
    #pragma unroll
    for (int i = 0; i < 4; i++) { rs[i][0] = 0.f; rs[i][1] = 0.f; }
    float acc[4][4][4];

    ISSUE(0);
    ISSUE(1);

    for (int t = 0; t < 72; t++) {
        int nt = t / 12, kt = t % 12;
        if (t < 71) CP_WAIT1(); else CP_WAIT0();
        __syncthreads();
        if (t + 2 < 72) ISSUE(t + 2);

        if (kt == 0) {
            #pragma unroll
            for (int i = 0; i < 4; i++)
                #pragma unroll
                for (int j = 0; j < 4; j++)
                    #pragma unroll
                    for (int qq = 0; qq < 4; qq++) acc[i][j][qq] = 0.f;
        }

        uint32_t stg = sb + (uint32_t)(t % 3) * STAGE_B;
        #pragma unroll
        for (int kk = 0; kk < 4; kk++) {
            uint32_t kb = ((uint32_t)(kk * 32) + l16) ^ sx;
            uint32_t af[4][4], th0[4], th1[4], tl0[4], tl1[4];

            #pragma unroll
            for (int i = 0; i < 4; i++)
                LDSM4(af[i], stg + A_OFF + aoff + (uint32_t)(i * 2048) + kb);
            LDSM4(th0, stg + BH_OFF + boff0 + kb);
            LDSM4(th1, stg + BH_OFF + boff1 + kb);

            // P1: x * w_hi
            #pragma unroll
            for (int i = 0; i < 4; i++) {
                MMAH(acc[i][0], af[i], th0[0], th0[2]);
                MMAH(acc[i][1], af[i], th0[1], th0[3]);
                MMAH(acc[i][2], af[i], th1[0], th1[2]);
                MMAH(acc[i][3], af[i], th1[1], th1[3]);
            }

            LDSM4(tl0, stg + BL_OFF + boff0 + kb);
            LDSM4(tl1, stg + BL_OFF + boff1 + kb);

            // P2: x * w_lo
            #pragma unroll
            for (int i = 0; i < 4; i++) {
                MMAH(acc[i][0], af[i], tl0[0], tl0[2]);
                MMAH(acc[i][1], af[i], tl0[1], tl0[3]);
                MMAH(acc[i][2], af[i], tl1[0], tl1[2]);
                MMAH(acc[i][3], af[i], tl1[1], tl1[3]);
            }
        }

        if (kt == 11) {
            #pragma unroll
            for (int j = 0; j < 4; j++) {
                int col = nt * 128 + wn * 32 + j * 8 + (lane & 3) * 2;
                float b1lo = __ldg(b1 + col), b1hi = __ldg(b1 + col + 1);
                float w2lo = __ldg(w2 + col), w2hi = __ldg(w2 + col + 1);
                #pragma unroll
                for (int i = 0; i < 4; i++) {
                    rs[i][0] += fmaxf(acc[i][j][0] * INV64 + b1lo, 0.f) * w2lo
                              + fmaxf(acc[i][j][1] * INV64 + b1hi, 0.f) * w2hi;
                    rs[i][1] += fmaxf(acc[i][j][2] * INV64 + b1lo, 0.f) * w2lo
                              + fmaxf(acc[i][j][3] * INV64 + b1hi, 0.f) * w2hi;
                }
            }
        }
    }
    #undef ISSUE

    // cross-thread row reduction: 16 contributors per row
    __syncthreads();
    int rcol = wn * 4 + (lane & 3);
    #pragma unroll
    for (int i = 0; i < 4; i++) {
        int row = wm * 64 + i * 16 + (lane >> 2);
        red[row * 17 + rcol] = rs[i][0];
        red[(row + 8) * 17 + rcol] = rs[i][1];
    }
    __syncthreads();
    if (tid < 256) {
        float s = b2[0];
        #pragma unroll
        for (int t = 0; t < 16; t++) s += red[tid * 17 + t];
        g_f[rowbase + tid] = s;
    }
}

// ---------------------------------------------------------------
// K4: out = f(ctx_n) + f(ent_n[argmax])
// ---------------------------------------------------------------
__global__ void k_combine(float* __restrict__ out) {
    int i = blockIdx.x * 256 + threadIdx.x;
    int bk = i / LL;
    out[i] = g_f[i] + g_f[NROWS + bk * LL + g_amax[i]];
}

extern "C" void kernel_launch(void* const* d_in, const int* in_sizes, int n_in,
                              void* d_out, int out_size) {
    const float* context = (const float*)d_in[0];
    const float* w1 = (const float*)d_in[1];
    const float* b1 = (const float*)d_in[2];
    const float* w2 = (const float*)d_in[3];
    const float* b2 = (const float*)d_in[4];
    float* out = (float*)d_out;

    k_prep_w1<<<DD, 256>>>(w1);
    k_normalize<<<NBK * 2 * LL, 192>>>(context);
    k_scores<<<NBK, 256>>>();
    cudaFuncSetAttribute(k_mlp_mma, cudaFuncAttributeMaxDynamicSharedMemorySize, MLP_SMEM);
    k_mlp_mma<<<TROWS / 256, 512, MLP_SMEM>>>(b1, w2, b2);
    k_combine<<<NROWS / 256, 256>>>(out);
}

// round 16
// speedup vs baseline: 2.0899x; 1.4635x over previous
#include <cuda_runtime.h>
#include <cuda_bf16.h>
#include <cuda_fp16.h>
#include <cstdint>

#define BB 4
#define KK 64
#define LL 128
#define DD 768
#define NBK (BB*KK)          // 256
#define NROWS (NBK*LL)       // 32768 per side
#define TROWS (2*NROWS)      // 65536

// ---------------- scratch ----------------
__device__ float g_ctx_n[(size_t)NROWS * DD];
__device__ float g_ent_n[(size_t)NROWS * DD];
__device__ __half g_xh[(size_t)TROWS * DD];          // normalized rows, fp16
__device__ __half g_w1t[(size_t)DD * DD];            // [n][k] = w1[k][n], fp16
__device__ float g_f[TROWS];
__device__ int   g_amax[NROWS];

// ---------------- helpers ----------------
__device__ __forceinline__ uint32_t smem_u32(const void* p) {
    uint32_t a;
    asm("{ .reg .u64 t; cvta.to.shared.u64 t, %1; cvt.u32.u64 %0, t; }" : "=r"(a) : "l"(p));
    return a;
}
#define CP_ASYNC16(sa, ga) \
    asm volatile("{ .reg .u64 g; cvta.to.global.u64 g, %1; cp.async.cg.shared.global [%0], [g], 16; }" \
        :: "r"(sa), "l"(ga) : "memory")
#define CP_COMMIT() asm volatile("cp.async.commit_group;" ::: "memory")
#define CP_WAIT2()  asm volatile("cp.async.wait_group 2;" ::: "memory")
#define CP_WAIT1()  asm volatile("cp.async.wait_group 1;" ::: "memory")
#define CP_WAIT0()  asm volatile("cp.async.wait_group 0;" ::: "memory")

#define LDSM4(r, a) \
    asm volatile("ldmatrix.sync.aligned.m8n8.x4.shared.b16 {%0,%1,%2,%3}, [%4];" \
        : "=r"((r)[0]), "=r"((r)[1]), "=r"((r)[2]), "=r"((r)[3]) : "r"(a))

#define MMAH(d, a, b0, b1) \
    asm volatile("mma.sync.aligned.m16n8k16.row.col.f32.f16.f16.f32 " \
        "{%0,%1,%2,%3},{%4,%5,%6,%7},{%8,%9},{%0,%1,%2,%3};" \
        : "+f"((d)[0]), "+f"((d)[1]), "+f"((d)[2]), "+f"((d)[3]) \
        : "r"((a)[0]), "r"((a)[1]), "r"((a)[2]), "r"((a)[3]), "r"(b0), "r"(b1))

// ---------- packed f32x2 (scores kernel) ----------
__device__ __forceinline__ unsigned long long pk2(float lo, float hi) {
    unsigned long long r;
    asm("mov.b64 %0, {%1,%2};" : "=l"(r) : "f"(lo), "f"(hi));
    return r;
}
__device__ __forceinline__ void upk2(unsigned long long v, float& lo, float& hi) {
    asm("mov.b64 {%0,%1}, %2;" : "=f"(lo), "=f"(hi) : "l"(v));
}
__device__ __forceinline__ void ffma2(unsigned long long& d,
                                      unsigned long long a, unsigned long long b) {
    asm("fma.rn.f32x2 %0, %1, %2, %0;" : "+l"(d) : "l"(a), "l"(b));
}

// ---------------------------------------------------------------
// K0: w1 -> transposed plain fp16
// ---------------------------------------------------------------
__global__ void __launch_bounds__(256) k_prep_w1(const float* __restrict__ w1) {
    int n = blockIdx.x;
    for (int k = threadIdx.x; k < DD; k += 256)
        g_w1t[(size_t)n * DD + k] = __float2half_rn(w1[(size_t)k * DD + n]);
}

// ---------------------------------------------------------------
// K1: normalize rows -> fp32 (scores) + fp16 (MLP)
// ---------------------------------------------------------------
__global__ void __launch_bounds__(192) k_normalize(const float* __restrict__ ctxt) {
    __shared__ float red[6];
    int r = blockIdx.x;
    int tid = threadIdx.x;
    const float4* src = (const float4*)(ctxt + (size_t)r * DD);
    float4 v = src[tid];
    float ss = v.x*v.x + v.y*v.y + v.z*v.z + v.w*v.w;
    #pragma unroll
    for (int o = 16; o; o >>= 1) ss += __shfl_xor_sync(0xffffffffu, ss, o);
    if ((tid & 31) == 0) red[tid >> 5] = ss;
    __syncthreads();
    float tot = red[0] + red[1] + red[2] + red[3] + red[4] + red[5];
    float inv = 1.0f / sqrtf(tot);
    int l  = r % LL;
    int s  = (r / LL) & 1;
    int bk = r / (2 * LL);
    size_t row32 = (size_t)bk * LL + l;
    float4 o = make_float4(v.x*inv, v.y*inv, v.z*inv, v.w*inv);
    ((float4*)((s == 0 ? g_ctx_n : g_ent_n) + row32 * DD))[tid] = o;
    size_t urow = (size_t)s * NROWS + row32;
    __half2* ph = (__half2*)(g_xh + urow * DD) + tid * 2;
    ph[0] = __floats2half2_rn(o.x, o.y);
    ph[1] = __floats2half2_rn(o.z, o.w);
}

// ---------------------------------------------------------------
// K2: fp32 cosine scores + argmax (exact; argmax is tie-sensitive)
// ---------------------------------------------------------------
__global__ void __launch_bounds__(256) k_scores() {
    __shared__ float As[16 * 128];
    __shared__ float Bs[16 * 128];
    __shared__ float sval[128 * 17];
    __shared__ int   sidx[128 * 17];

    int bk = blockIdx.x;
    const float* ctxp = g_ctx_n + (size_t)bk * LL * DD;
    const float* entp = g_ent_n + (size_t)bk * LL * DD;
    int tid = threadIdx.x;
    int tm = tid & 15, tn = tid >> 4;
    int m0 = tm * 8, n0 = tn * 8;

    unsigned long long c2[8][4];
    #pragma unroll
    for (int i = 0; i < 8; i++)
        #pragma unroll
        for (int j = 0; j < 4; j++) c2[i][j] = 0ULL;

    int mrow = tid & 127;
    int hf = tid >> 7;

    for (int kt = 0; kt < 48; kt++) {
        __syncthreads();
        const float4* a4 = (const float4*)(ctxp + (size_t)mrow * DD + kt * 16);
        const float4* b4 = (const float4*)(entp + (size_t)mrow * DD + kt * 16);
        #pragma unroll
        for (int u = 0; u < 2; u++) {
            int kq = hf * 2 + u;
            float4 v = a4[kq];
            int k4 = kq * 4;
            As[(k4+0)*128+mrow] = v.x; As[(k4+1)*128+mrow] = v.y;
            As[(k4+2)*128+mrow] = v.z; As[(k4+3)*128+mrow] = v.w;
            v = b4[kq];
            Bs[(k4+0)*128+mrow] = v.x; Bs[(k4+1)*128+mrow] = v.y;
            Bs[(k4+2)*128+mrow] = v.z; Bs[(k4+3)*128+mrow] = v.w;
        }
        __syncthreads();
        #pragma unroll
        for (int kk = 0; kk < 16; kk++) {
            float4 aA = *(const float4*)(As + kk*128 + m0);
            float4 aB = *(const float4*)(As + kk*128 + m0 + 4);
            float4 bA = *(const float4*)(Bs + kk*128 + n0);
            float4 bB = *(const float4*)(Bs + kk*128 + n0 + 4);
            unsigned long long ap[8], bp[4];
            ap[0]=pk2(aA.x,aA.x); ap[1]=pk2(aA.y,aA.y); ap[2]=pk2(aA.z,aA.z); ap[3]=pk2(aA.w,aA.w);
            ap[4]=pk2(aB.x,aB.x); ap[5]=pk2(aB.y,aB.y); ap[6]=pk2(aB.z,aB.z); ap[7]=pk2(aB.w,aB.w);
            bp[0]=pk2(bA.x,bA.y); bp[1]=pk2(bA.z,bA.w); bp[2]=pk2(bB.x,bB.y); bp[3]=pk2(bB.z,bB.w);
            #pragma unroll
            for (int i = 0; i < 8; i++)
                #pragma unroll
                for (int j = 0; j < 4; j++) ffma2(c2[i][j], ap[i], bp[j]);
        }
    }

    #pragma unroll
    for (int i = 0; i < 8; i++) {
        float bv = -3.4e38f; int bi = 0;
        #pragma unroll
        for (int j = 0; j < 4; j++) {
            float lo, hi; upk2(c2[i][j], lo, hi);
            int n = n0 + 2 * j;
            if (lo > bv) { bv = lo; bi = n; }
            if (hi > bv) { bv = hi; bi = n + 1; }
        }
        sval[(m0 + i) * 17 + tn] = bv;
        sidx[(m0 + i) * 17 + tn] = bi;
    }
    __syncthreads();
    if (tid < 128) {
        float bv = sval[tid * 17]; int bi = sidx[tid * 17];
        #pragma unroll
        for (int t = 1; t < 16; t++) {
            float v = sval[tid * 17 + t];
            if (v > bv) { bv = v; bi = sidx[tid * 17 + t]; }
        }
        g_amax[bk * LL + tid] = bi;
    }
}

// ---------------------------------------------------------------
// K3 v8: MLP single-product plain fp16 (A fp16, W fp16).
// 512 threads, tile 256 rows x 128 cols, k=64 stages (72 total),
// 4-stage 48KB ring w/ 3-deep lookahead (wait_group 2), grid 256.
// Warp tile 64x32 (4M x 4N).
// ---------------------------------------------------------------
#define A_OFF 0
#define B_OFF 32768
#define STAGE_B 49152                        // 48 KB
#define NSTAGE 4
#define MLP_SMEM (NSTAGE * STAGE_B + 256 * 17 * 4)   // 196608 + 17408 = 214016

__global__ void __launch_bounds__(512, 1) k_mlp_mma(const float* __restrict__ b1,
                                                    const float* __restrict__ w2,
                                                    const float* __restrict__ b2) {
    extern __shared__ char sm[];
    uint32_t sb = smem_u32(sm);
    float* red = (float*)(sm + NSTAGE * STAGE_B);

    int tid = threadIdx.x, lane = tid & 31, w = tid >> 5;
    int wm = w & 3, wn = w >> 2;
    size_t rowbase = (size_t)blockIdx.x * 256;

    // ---- producer mapping ----
    // A: 256 rows x 128B; 2 threads/row, 64B (4x16B) each
    int lr = tid >> 1;
    uint32_t a_cb = (uint32_t)(tid & 1) * 64;
    uint32_t a_swz = ((uint32_t)(lr & 7)) << 4;
    uint32_t a_srow = (uint32_t)lr * 128;
    const char* gA = (const char*)(g_xh + (rowbase + (size_t)lr) * DD) + a_cb;
    // B: 128 n-rows x 128B; 4 threads/row, 32B (2x16B) each
    int nr = tid >> 2;
    int q  = tid & 3;
    uint32_t b_cb = (uint32_t)q * 32;
    uint32_t b_swz = ((uint32_t)(nr & 7)) << 4;
    uint32_t b_srow = (uint32_t)nr * 128;

    #define ISSUE(t) do {                                                        \
        int _nt = (t) / 12, _kt = (t) % 12;                                       \
        uint32_t _st = sb + (uint32_t)((t) % NSTAGE) * STAGE_B;                   \
        const char* _ga = gA + _kt * 128;                                         \
        _Pragma("unroll")                                                         \
        for (int _q4 = 0; _q4 < 4; _q4++)                                         \
            CP_ASYNC16(_st + A_OFF + a_srow + ((a_cb + _q4 * 16) ^ a_swz),        \
                       _ga + _q4 * 16);                                           \
        const char* _gb = (const char*)(g_w1t                                     \
            + ((size_t)(_nt * 128 + nr)) * DD + _kt * 64) + b_cb;                 \
        uint32_t _sb2 = _st + B_OFF + b_srow;                                     \
        CP_ASYNC16(_sb2 + ((b_cb)      ^ b_swz), _gb);                            \
        CP_ASYNC16(_sb2 + ((b_cb + 16) ^ b_swz), _gb + 16);                       \
        CP_COMMIT();                                                              \
    } while (0)

    // ---- consumer (ldmatrix) mapping ----
    int l15 = lane & 15;
    uint32_t sx = ((uint32_t)(lane & 7)) << 4;
    uint32_t l16 = (uint32_t)(lane >> 4) * 16;
    uint32_t aoff  = (uint32_t)(wm * 64 + l15) * 128;
    uint32_t boff0 = (uint32_t)(wn * 32 + l15) * 128;
    uint32_t boff1 = boff0 + 2048;

    float rs[4][2];
    #pragma unroll
    for (int i = 0; i < 4; i++) { rs[i][0] = 0.f; rs[i][1] = 0.f; }
    float acc[4][4][4];

    ISSUE(0);
    ISSUE(1);
    ISSUE(2);

    for (int t = 0; t < 72; t++) {
        int nt = t / 12, kt = t % 12;
        if (t < 70) CP_WAIT2(); else if (t == 70) CP_WAIT1(); else CP_WAIT0();
        __syncthreads();
        if (t + 3 < 72) ISSUE(t + 3);

        if (kt == 0) {
            #pragma unroll
            for (int i = 0; i < 4; i++)
                #pragma unroll
                for (int j = 0; j < 4; j++)
                    #pragma unroll
                    for (int qq = 0; qq < 4; qq++) acc[i][j][qq] = 0.f;
        }

        uint32_t stg = sb + (uint32_t)(t % NSTAGE) * STAGE_B;
        #pragma unroll
        for (int kk = 0; kk < 4; kk++) {
            uint32_t kb = ((uint32_t)(kk * 32) + l16) ^ sx;
            uint32_t af[4][4], th0[4], th1[4];

            #pragma unroll
            for (int i = 0; i < 4; i++)
                LDSM4(af[i], stg + A_OFF + aoff + (uint32_t)(i * 2048) + kb);
            LDSM4(th0, stg + B_OFF + boff0 + kb);
            LDSM4(th1, stg + B_OFF + boff1 + kb);

            #pragma unroll
            for (int i = 0; i < 4; i++) {
                MMAH(acc[i][0], af[i], th0[0], th0[2]);
                MMAH(acc[i][1], af[i], th0[1], th0[3]);
                MMAH(acc[i][2], af[i], th1[0], th1[2]);
                MMAH(acc[i][3], af[i], th1[1], th1[3]);
            }
        }

        if (kt == 11) {
            #pragma unroll
            for (int j = 0; j < 4; j++) {
                int col = nt * 128 + wn * 32 + j * 8 + (lane & 3) * 2;
                float b1lo = __ldg(b1 + col), b1hi = __ldg(b1 + col + 1);
                float w2lo = __ldg(w2 + col), w2hi = __ldg(w2 + col + 1);
                #pragma unroll
                for (int i = 0; i < 4; i++) {
                    rs[i][0] += fmaxf(acc[i][j][0] + b1lo, 0.f) * w2lo
                              + fmaxf(acc[i][j][1] + b1hi, 0.f) * w2hi;
                    rs[i][1] += fmaxf(acc[i][j][2] + b1lo, 0.f) * w2lo
                              + fmaxf(acc[i][j][3] + b1hi, 0.f) * w2hi;
                }
            }
        }
    }
    #undef ISSUE

    // cross-thread row reduction: 16 contributors per row
    __syncthreads();
    int rcol = wn * 4 + (lane & 3);
    #pragma unroll
    for (int i = 0; i < 4; i++) {
        int row = wm * 64 + i * 16 + (lane >> 2);
        red[row * 17 + rcol] = rs[i][0];
        red[(row + 8) * 17 + rcol] = rs[i][1];
    }
    __syncthreads();
    if (tid < 256) {
        float s = b2[0];
        #pragma unroll
        for (int t = 0; t < 16; t++) s += red[tid * 17 + t];
        g_f[rowbase + tid] = s;
    }
}

// ---------------------------------------------------------------
// K4: out = f(ctx_n) + f(ent_n[argmax])
// ---------------------------------------------------------------
__global__ void k_combine(float* __restrict__ out) {
    int i = blockIdx.x * 256 + threadIdx.x;
    int bk = i / LL;
    out[i] = g_f[i] + g_f[NROWS + bk * LL + g_amax[i]];
}

extern "C" void kernel_launch(void* const* d_in, const int* in_sizes, int n_in,
                              void* d_out, int out_size) {
    const float* context = (const float*)d_in[0];
    const float* w1 = (const float*)d_in[1];
    const float* b1 = (const float*)d_in[2];
    const float* w2 = (const float*)d_in[3];
    const float* b2 = (const float*)d_in[4];
    float* out = (float*)d_out;

    k_prep_w1<<<DD, 256>>>(w1);
    k_normalize<<<NBK * 2 * LL, 192>>>(context);
    k_scores<<<NBK, 256>>>();
    cudaFuncSetAttribute(k_mlp_mma, cudaFuncAttributeMaxDynamicSharedMemorySize, MLP_SMEM);
    k_mlp_mma<<<TROWS / 256, 512, MLP_SMEM>>>(b1, w2, b2);
    k_combine<<<NROWS / 256, 256>>>(out);
}